// round 1
// baseline (speedup 1.0000x reference)
#include <cuda_runtime.h>
#include <cuda_bf16.h>

// CasamentoMult on GB300: collapses the [2, N-2] Toeplitz-window MMD expression
// into one streaming pass.  sigma = 1/sqrt(2*pi) makes log_sqrt_pi == 0, so each
// pair term is exp(-pi * diff^2) = 2^(C2 * diff^2), C2 = -pi*log2(e).
//
//  total = NE + sum_{k=0}^{NE-1} [ 0.5*(e(dy)+e(dd) - e(d1-y0) - e(d0-y1)) - e(d0-y0) ]
//             + 0.5*e(d[0]-y[0]) - 0.5*e(d[NE]-y[NE]),   NE = N-2.

#define NBLK 1184          // 148 SMs * 8
#define NTHR 256

__device__ float g_partials[NBLK];

__device__ __forceinline__ float gex(float x) {
    // 2^(C2 * x*x) == exp(-pi*x*x);  ex2.approx flushes very negative args to 0.
    float a = (x * -4.532360141827194f) * x;   // C2 = -pi * log2(e)
    float r;
    asm("ex2.approx.f32 %0, %1;" : "=f"(r) : "f"(a));
    return r;
}

__global__ void __launch_bounds__(NTHR)
casa_main(const float* __restrict__ d, const float* __restrict__ y, int ngroups) {
    float accA = 0.f;   // ey + ed - c01 - c10   (weight 0.5 applied once at end)
    float accS = 0.f;   // s[k]                  (weight -1)
    const int stride = gridDim.x * blockDim.x;

    for (int g = blockIdx.x * blockDim.x + threadIdx.x; g < ngroups; g += stride) {
        const int base = g << 2;
        const float4 dv = *reinterpret_cast<const float4*>(d + base);
        const float4 yv = *reinterpret_cast<const float4*>(y + base);
        const float d4 = __ldg(d + base + 4);
        const float y4 = __ldg(y + base + 4);

        // k = base
        accA += gex(yv.y - yv.x) + gex(dv.y - dv.x) - gex(dv.y - yv.x) - gex(dv.x - yv.y);
        accS += gex(dv.x - yv.x);
        // k = base + 1
        accA += gex(yv.z - yv.y) + gex(dv.z - dv.y) - gex(dv.z - yv.y) - gex(dv.y - yv.z);
        accS += gex(dv.y - yv.y);
        // k = base + 2
        accA += gex(yv.w - yv.z) + gex(dv.w - dv.z) - gex(dv.w - yv.z) - gex(dv.z - yv.w);
        accS += gex(dv.z - yv.z);
        // k = base + 3
        accA += gex(y4 - yv.w) + gex(d4 - dv.w) - gex(d4 - yv.w) - gex(dv.w - y4);
        accS += gex(dv.w - yv.w);
    }

    float acc = 0.5f * accA - accS;

    // warp reduce
    #pragma unroll
    for (int o = 16; o; o >>= 1) acc += __shfl_down_sync(0xffffffffu, acc, o);

    __shared__ float sh[NTHR / 32];
    const int lane = threadIdx.x & 31;
    const int w    = threadIdx.x >> 5;
    if (lane == 0) sh[w] = acc;
    __syncthreads();
    if (w == 0) {
        float v = (lane < NTHR / 32) ? sh[lane] : 0.f;
        #pragma unroll
        for (int o = 4; o; o >>= 1) v += __shfl_down_sync(0xffffffffu, v, o);
        if (lane == 0) g_partials[blockIdx.x] = v;
    }
}

__global__ void __launch_bounds__(256)
casa_finish(const float* __restrict__ d, const float* __restrict__ y,
            int NE, int ngroups, int nblocks, float* __restrict__ out) {
    const int tid = threadIdx.x;
    double v = 0.0;
    for (int i = tid; i < nblocks; i += blockDim.x)
        v += (double)g_partials[i];

    if (tid == 0) {
        // tail elements not covered by the vectorized groups
        for (int k = 4 * ngroups; k < NE; k++) {
            float d0 = d[k], d1 = d[k + 1], y0 = y[k], y1 = y[k + 1];
            float a = gex(y1 - y0) + gex(d1 - d0) - gex(d1 - y0) - gex(d0 - y1);
            v += 0.5 * (double)a - (double)gex(d0 - y0);
        }
        // boundary corrections from the telescoped s[m] sums, plus the constant
        v += 0.5 * ((double)gex(d[0] - y[0]) - (double)gex(d[NE] - y[NE]));
        v += (double)NE;
    }

    // block-wide double reduction (deterministic, no atomics)
    #pragma unroll
    for (int o = 16; o; o >>= 1) v += __shfl_down_sync(0xffffffffu, v, o);

    __shared__ double shd[8];
    const int lane = tid & 31, w = tid >> 5;
    if (lane == 0) shd[w] = v;
    __syncthreads();
    if (w == 0) {
        double t = (lane < 8) ? shd[lane] : 0.0;
        #pragma unroll
        for (int o = 4; o; o >>= 1) t += __shfl_down_sync(0xffffffffu, t, o);
        if (lane == 0) out[0] = (float)t;
    }
}

extern "C" void kernel_launch(void* const* d_in, const int* in_sizes, int n_in,
                              void* d_out, int out_size) {
    const float* d = (const float*)d_in[0];
    const float* y = (const float*)d_in[1];
    float* out = (float*)d_out;

    const int n  = in_sizes[0];
    const int NE = n - 2;               // 4,000,000 for N = 4,000,002
    const int ngroups = NE / 4;         // each group covers 4 consecutive k

    casa_main<<<NBLK, NTHR>>>(d, y, ngroups);
    casa_finish<<<1, 256>>>(d, y, NE, ngroups, NBLK, out);
}

// round 2
// speedup vs baseline: 1.0173x; 1.0173x over previous
#include <cuda_runtime.h>
#include <cuda_bf16.h>

// CasamentoMult on GB300, fused single-kernel version.
// sigma = 1/sqrt(2*pi) makes log_sqrt_pi == 0, so each pair term is
// exp(-pi*diff^2) = 2^(C2*diff^2), C2 = -pi*log2(e).  The [2,N-2] Toeplitz
// MMD collapses (diagonal terms -> constant NE; cross-diagonals telescope) to:
//
//  total = NE + sum_{k=0}^{NE-1} [ 0.5*(e(y1-y0)+e(d1-d0) - e(d1-y0) - e(d0-y1)) - e(d0-y0) ]
//             + 0.5*e(d[0]-y[0]) - 0.5*e(d[NE]-y[NE]),   NE = N-2.
//
// Single kernel: grid-stride accumulate -> per-block partial -> threadfence +
// atomic ticket -> LAST block does the deterministic double-precision finish
// (fixed-order reads of g_partials) and resets the ticket for graph replay.

#define NBLK 1184          // 148 SMs * 8
#define NTHR 256

__device__ float    g_partials[NBLK];
__device__ unsigned g_ticket = 0;

__device__ __forceinline__ float gex(float x) {
    // 2^(C2 * x*x) == exp(-pi*x*x);  ex2.approx flushes very negative args to 0.
    float a = (x * -4.532360141827194f) * x;   // C2 = -pi * log2(e)
    float r;
    asm("ex2.approx.f32 %0, %1;" : "=f"(r) : "f"(a));
    return r;
}

__global__ void __launch_bounds__(NTHR)
casa_fused(const float* __restrict__ d, const float* __restrict__ y,
           int NE, int ngroups, float* __restrict__ out) {
    float accA = 0.f;   // e(yy)+e(dd) - c01 - c10   (weight 0.5 applied at end)
    float accS = 0.f;   // e(d0-y0)                  (weight -1)
    const int stride = gridDim.x * blockDim.x;

    for (int g = blockIdx.x * blockDim.x + threadIdx.x; g < ngroups; g += stride) {
        const int base = g << 2;
        const float4 dv = *reinterpret_cast<const float4*>(d + base);
        const float4 yv = *reinterpret_cast<const float4*>(y + base);
        const float d4 = __ldg(d + base + 4);
        const float y4 = __ldg(y + base + 4);

        accA += gex(yv.y - yv.x) + gex(dv.y - dv.x) - gex(dv.y - yv.x) - gex(dv.x - yv.y);
        accS += gex(dv.x - yv.x);
        accA += gex(yv.z - yv.y) + gex(dv.z - dv.y) - gex(dv.z - yv.y) - gex(dv.y - yv.z);
        accS += gex(dv.y - yv.y);
        accA += gex(yv.w - yv.z) + gex(dv.w - dv.z) - gex(dv.w - yv.z) - gex(dv.z - yv.w);
        accS += gex(dv.z - yv.z);
        accA += gex(y4 - yv.w) + gex(d4 - dv.w) - gex(d4 - yv.w) - gex(dv.w - y4);
        accS += gex(dv.w - yv.w);
    }

    float acc = 0.5f * accA - accS;

    // block reduce (float)
    #pragma unroll
    for (int o = 16; o; o >>= 1) acc += __shfl_down_sync(0xffffffffu, acc, o);

    __shared__ float sh[NTHR / 32];
    __shared__ bool  s_last;
    const int lane = threadIdx.x & 31;
    const int w    = threadIdx.x >> 5;
    if (lane == 0) sh[w] = acc;
    __syncthreads();
    if (threadIdx.x == 0) {
        float v = 0.f;
        #pragma unroll
        for (int i = 0; i < NTHR / 32; i++) v += sh[i];
        g_partials[blockIdx.x] = v;
        __threadfence();
        unsigned t = atomicAdd(&g_ticket, 1u);
        s_last = (t == (unsigned)gridDim.x - 1u);
    }
    __syncthreads();
    if (!s_last) return;

    // ---- last block: deterministic double-precision finish ----
    const int tid = threadIdx.x;
    double v = 0.0;
    for (int i = tid; i < NBLK; i += NTHR)      // fixed-order per thread
        v += (double)g_partials[i];

    if (tid == 0) {
        for (int k = 4 * ngroups; k < NE; k++) {  // tail (empty when NE%4==0)
            float d0 = d[k], d1 = d[k + 1], y0 = y[k], y1 = y[k + 1];
            float a = gex(y1 - y0) + gex(d1 - d0) - gex(d1 - y0) - gex(d0 - y1);
            v += 0.5 * (double)a - (double)gex(d0 - y0);
        }
        v += 0.5 * ((double)gex(d[0] - y[0]) - (double)gex(d[NE] - y[NE]));
        v += (double)NE;
    }

    #pragma unroll
    for (int o = 16; o; o >>= 1) v += __shfl_down_sync(0xffffffffu, v, o);

    __shared__ double shd[NTHR / 32];
    if (lane == 0) shd[w] = v;
    __syncthreads();
    if (tid == 0) {
        double t = 0.0;
        #pragma unroll
        for (int i = 0; i < NTHR / 32; i++) t += shd[i];
        out[0] = (float)t;
        g_ticket = 0;                 // reset for next graph replay
    }
}

extern "C" void kernel_launch(void* const* d_in, const int* in_sizes, int n_in,
                              void* d_out, int out_size) {
    const float* d = (const float*)d_in[0];
    const float* y = (const float*)d_in[1];
    float* out = (float*)d_out;

    const int n  = in_sizes[0];
    const int NE = n - 2;               // 4,000,000 for N = 4,000,002
    const int ngroups = NE / 4;

    casa_fused<<<NBLK, NTHR>>>(d, y, NE, ngroups, out);
}